// round 15
// baseline (speedup 1.0000x reference)
#include <cuda_runtime.h>
#include <cuda_bf16.h>

#define NH 6
#define HD 32
#define NTOK 64
#define HIDDEN 512
#define TBL 225
#define HW 65536

// Per-window Q/K buffer: row n at n*36 + ((n>>2)&15) words; 64 rows + pad.
#define STQK 36
#define SWQK(n) ((n) * STQK + (((n) >> 2) & 15))
#define QKW 2320          // words per Q or K window buffer (64*36+16)
// V: [32][68] words; words 0..31 = m-pair hi, 32..63 = lo.
#define VW 2176           // 32*68
#define LOG2E 1.4426950408889634f

// dynamic smem word offsets (2 windows per CTA)
#define OFF_SQ 0
#define OFF_SK (2 * QKW)                 // 4640
#define OFF_SV (4 * QKW)                 // 9280
#define SMEM_WORDS (OFF_SV + 2 * VW)     // 13632 words = 54528 B

// m16n8k16 row.col f32.bf16.bf16.f32
#define MMA(D, A, b0, b1) \
    asm("mma.sync.aligned.m16n8k16.row.col.f32.bf16.bf16.f32 " \
        "{%0,%1,%2,%3},{%4,%5,%6,%7},{%8,%9},{%0,%1,%2,%3};" \
        : "+f"(D[0]), "+f"(D[1]), "+f"(D[2]), "+f"(D[3]) \
        : "r"(A[0]), "r"(A[1]), "r"(A[2]), "r"(A[3]), "r"(b0), "r"(b1))

__device__ __forceinline__ unsigned pack2(float lo, float hi) {
    unsigned r;
    asm("cvt.rn.bf16x2.f32 %0, %1, %2;" : "=r"(r) : "f"(hi), "f"(lo));
    return r;  // low half = lo, high half = hi
}
__device__ __forceinline__ float bflo(unsigned w) { return __uint_as_float(w << 16); }
__device__ __forceinline__ float bfhi(unsigned w) { return __uint_as_float(w & 0xffff0000u); }
__device__ __forceinline__ float ex2f(float x) {
    float y;
    asm("ex2.approx.ftz.f32 %0, %1;" : "=f"(y) : "f"(x));
    return y;
}

// device-global scratch (no allocations allowed)
__device__ float g_bt[TBL * NH];
__device__ float g_hscale[NH];       // exp(min(ls,max)) * rsqrt(hd) * log2e
__device__ float g_bias[NH * NTOK * NTOK];  // 16*sigmoid(..) * log2e

// ---------------------------------------------------------------------------
// Kernel 0a: CPB MLP, one block per table row (225 blocks) + head scales.
// ---------------------------------------------------------------------------
__global__ void __launch_bounds__(128) bias_mlp_kernel(
    const float* __restrict__ table,
    const float* __restrict__ logit_scale,
    const float* __restrict__ w1,
    const float* __restrict__ b1,
    const float* __restrict__ w2) {
    const int row = blockIdx.x;
    const int tid = threadIdx.x;

    if (row == 0 && tid < NH) {
        const float LOGIT_MAX = 4.605170185988091368f; // log(100)
        g_hscale[tid] = expf(fminf(logit_scale[tid], LOGIT_MAX)) * rsqrtf((float)HD) * LOG2E;
    }

    const float t0 = table[row * 2 + 0];
    const float t1 = table[row * 2 + 1];
    float acc[NH];
#pragma unroll
    for (int h = 0; h < NH; h++) acc[h] = 0.f;

    for (int j = tid; j < HIDDEN; j += 128) {
        float hv = fmaf(t0, w1[j], fmaf(t1, w1[HIDDEN + j], b1[j]));
        hv = fmaxf(hv, 0.f);
#pragma unroll
        for (int h = 0; h < NH; h++) acc[h] = fmaf(hv, w2[j * NH + h], acc[h]);
    }

#pragma unroll
    for (int h = 0; h < NH; h++) {
#pragma unroll
        for (int o = 16; o > 0; o >>= 1)
            acc[h] += __shfl_xor_sync(0xffffffffu, acc[h], o);
    }
    __shared__ float red[4][NH];
    const int warp = tid >> 5;
    if ((tid & 31) == 0) {
#pragma unroll
        for (int h = 0; h < NH; h++) red[warp][h] = acc[h];
    }
    __syncthreads();
    if (tid == 0) {
#pragma unroll
        for (int h = 0; h < NH; h++)
            g_bt[row * NH + h] = red[0][h] + red[1][h] + red[2][h] + red[3][h];
    }
}

// ---------------------------------------------------------------------------
// Kernel 0b: expand bias -> g_bias[h][n][m] = 16*sigmoid(bt[idx][h]) * log2e
// ---------------------------------------------------------------------------
__global__ void bias_gather_kernel(const int* __restrict__ index) {
    int gid = blockIdx.x * blockDim.x + threadIdx.x;
    if (gid >= NH * NTOK * NTOK) return;
    int h = gid >> 12;
    int nm = gid & 4095;
    int r = index[nm];
    float bv = g_bt[r * NH + h];
    g_bias[gid] = (16.f / (1.f + __expf(-bv))) * LOG2E;
}

// ---------------------------------------------------------------------------
// Main kernel: one CTA per (2-window strip, head). 256 threads, 4 CTAs/SM.
//  Strip-coalesced staging; bf16x3 mma.sync; bias+mask read from L2 in
//  the epilogue (32 warps/SM cover the latency).
// ---------------------------------------------------------------------------
__global__ void __launch_bounds__(256, 4) win_attn_kernel(
    const float* __restrict__ qkv,
    const float* __restrict__ mask,
    const float* __restrict__ bias,
    float* __restrict__ out)
{
    extern __shared__ __align__(16) unsigned dyn[];
    unsigned* const sq_all = dyn + OFF_SQ;
    unsigned* const sk_all = dyn + OFF_SK;
    unsigned* const sv_all = dyn + OFF_SV;

    const int tid = threadIdx.x;
    const int bid = blockIdx.x;
    const int h = bid % NH;
    const int s = bid / NH;             // 0..1023 strips
    const int b = s >> 9;               // batch
    const int sl = s & 511;
    const int wy = sl >> 4;             // window row 0..31
    const int sx = sl & 15;             // strip col 0..15 (2 windows each)
    const int y0 = wy * 8 + 4;
    const int x0s = sx * 16 + 4;        // strip x origin (shifted by roll)

    // channel = t*384 + b*192 + h*32 + d   (qkv is (3,B,192,H,W))
    const int chbase = b * 192 + h * 32;

    // ---- stage Q,K: strip-coalesced; unit = (tensor, k-pair, row, float4col) ----
#pragma unroll
    for (int l = 0; l < 4; l++) {
        int u = tid + l * 256;          // 0..1023
        int t = u >> 9;                 // 0 = q, 1 = k
        int rem = u & 511;
        int kp = rem >> 5;              // 0..15
        int i = (rem >> 2) & 7;         // window row
        int o4 = rem & 3;               // float4 col within strip (2 windows)
        int y = (y0 + i) & 255;
        int x = (x0s + 4 * o4) & 255;   // 4-aligned; no intra-float4 wrap
        const float* basep = qkv + (chbase + t * 384 + 2 * kp) * HW + y * 256 + x;
        float4 v0 = *(const float4*)basep;          // channel 2*kp
        float4 v1 = *(const float4*)(basep + HW);   // channel 2*kp+1
        int wloc = o4 >> 1;
        int j0 = (o4 & 1) << 2;
        int n = i * 8 + j0;
        unsigned* rowbase = ((t == 0) ? sq_all : sk_all) + wloc * QKW;
        float a0[4] = {v0.x, v0.y, v0.z, v0.w};
        float a1[4] = {v1.x, v1.y, v1.z, v1.w};
#pragma unroll
        for (int e = 0; e < 4; e++) {
            unsigned hw_ = pack2(a0[e], a1[e]);
            unsigned lw_ = pack2(a0[e] - bflo(hw_), a1[e] - bfhi(hw_));
            int ro = SWQK(n + e);
            rowbase[ro + kp] = hw_;
            rowbase[ro + 16 + kp] = lw_;
        }
    }
    // ---- stage V: strip-coalesced ----
#pragma unroll
    for (int l = 0; l < 4; l++) {
        int u = tid + l * 256;          // 0..1023
        int d = u >> 5;                 // 0..31
        int i = (u >> 2) & 7;
        int o4 = u & 3;
        int y = (y0 + i) & 255;
        int x = (x0s + 4 * o4) & 255;
        float4 v = *(const float4*)(qkv + (chbase + 768 + d) * HW + y * 256 + x);
        int wloc = o4 >> 1;
        int j0 = (o4 & 1) << 2;
        int n = i * 8 + j0;
        unsigned* svw = sv_all + wloc * VW;
        unsigned h0 = pack2(v.x, v.y);
        unsigned h1 = pack2(v.z, v.w);
        unsigned l0 = pack2(v.x - bflo(h0), v.y - bfhi(h0));
        unsigned l1 = pack2(v.z - bflo(h1), v.w - bfhi(h1));
        *(uint2*)&svw[d * 68 + (n >> 1)] = make_uint2(h0, h1);
        *(uint2*)&svw[d * 68 + 32 + (n >> 1)] = make_uint2(l0, l1);
    }
    __syncthreads();

    const int lane = tid & 31;
    const int wid = tid >> 5;           // 0..7
    const int wloc = wid >> 2;          // window slot 0..1
    const int wrp = wid & 3;            // warp within window
    const int r = lane >> 2;            // groupID
    const int cq = lane & 3;            // threadID in group
    const int rowA = wrp * 16 + r;      // token row (half A); half B = +8

    const unsigned* sqw = sq_all + wloc * QKW;
    const unsigned* skw = sk_all + wloc * QKW;
    const unsigned* svw = sv_all + wloc * VW;
    const int x0 = x0s + 8 * wloc;      // this window's x origin

    // ---- QK^T: A fragments (Q) hoisted; 8 n-tiles x 2 k-steps x 3 splits ----
    unsigned ah[2][4], al[2][4];
#pragma unroll
    for (int ks = 0; ks < 2; ks++) {
        const unsigned* q0 = sqw + SWQK(rowA) + 8 * ks + cq;
        const unsigned* q1 = sqw + SWQK(rowA + 8) + 8 * ks + cq;
        ah[ks][0] = q0[0];  ah[ks][1] = q1[0];  ah[ks][2] = q0[4];  ah[ks][3] = q1[4];
        al[ks][0] = q0[16]; al[ks][1] = q1[16]; al[ks][2] = q0[20]; al[ks][3] = q1[20];
    }

    float D[8][4];
#pragma unroll
    for (int t = 0; t < 8; t++)
#pragma unroll
        for (int c = 0; c < 4; c++) D[t][c] = 0.f;

#pragma unroll
    for (int nt = 0; nt < 8; nt++) {
#pragma unroll
        for (int ks = 0; ks < 2; ks++) {
            const unsigned* kp = skw + SWQK(nt * 8 + r) + 8 * ks + cq;
            unsigned bh0 = kp[0], bh1 = kp[4];
            unsigned bl0 = kp[16], bl1 = kp[20];
            MMA(D[nt], ah[ks], bh0, bh1);
            MMA(D[nt], ah[ks], bl0, bl1);
            MMA(D[nt], al[ks], bh0, bh1);
        }
    }

    // ---- softmax IN PLACE in D, log2 domain; bias+mask from L2 ----
    const float scale2 = g_hscale[h];   // includes log2e
    const float* mask_w = mask + (wy * 32 + sx * 2 + wloc) * 4096;
    const float* bA_p = bias + h * 4096 + rowA * 64 + 2 * cq;
    const float* mA_p = mask_w + rowA * 64 + 2 * cq;
#pragma unroll
    for (int t = 0; t < 8; t++) {
        float2 bA = *(const float2*)(bA_p + t * 8);
        float2 mA = *(const float2*)(mA_p + t * 8);
        float2 bB = *(const float2*)(bA_p + 512 + t * 8);   // (rowA+8)*64
        float2 mB = *(const float2*)(mA_p + 512 + t * 8);
        D[t][0] = fmaf(D[t][0], scale2, fmaf(mA.x, LOG2E, bA.x));
        D[t][1] = fmaf(D[t][1], scale2, fmaf(mA.y, LOG2E, bA.y));
        D[t][2] = fmaf(D[t][2], scale2, fmaf(mB.x, LOG2E, bB.x));
        D[t][3] = fmaf(D[t][3], scale2, fmaf(mB.y, LOG2E, bB.y));
    }
    float mxA = -1e30f, mxB = -1e30f;
#pragma unroll
    for (int t = 0; t < 8; t++) {
        mxA = fmaxf(mxA, fmaxf(D[t][0], D[t][1]));
        mxB = fmaxf(mxB, fmaxf(D[t][2], D[t][3]));
    }
    mxA = fmaxf(mxA, __shfl_xor_sync(0xffffffffu, mxA, 1));
    mxA = fmaxf(mxA, __shfl_xor_sync(0xffffffffu, mxA, 2));
    mxB = fmaxf(mxB, __shfl_xor_sync(0xffffffffu, mxB, 1));
    mxB = fmaxf(mxB, __shfl_xor_sync(0xffffffffu, mxB, 2));

    // progressive: exp, sum, pack P (hi/lo); D dies as ph/pl born
    unsigned ph[4][4], pl[4][4];
    float smA = 0.f, smB = 0.f;
#pragma unroll
    for (int ks = 0; ks < 4; ks++) {
        float e00 = ex2f(D[2 * ks][0] - mxA);
        float e01 = ex2f(D[2 * ks][1] - mxA);
        float e02 = ex2f(D[2 * ks][2] - mxB);
        float e03 = ex2f(D[2 * ks][3] - mxB);
        float e10 = ex2f(D[2 * ks + 1][0] - mxA);
        float e11 = ex2f(D[2 * ks + 1][1] - mxA);
        float e12 = ex2f(D[2 * ks + 1][2] - mxB);
        float e13 = ex2f(D[2 * ks + 1][3] - mxB);
        smA += e00 + e01 + e10 + e11;
        smB += e02 + e03 + e12 + e13;
        ph[ks][0] = pack2(e00, e01);
        ph[ks][1] = pack2(e02, e03);
        ph[ks][2] = pack2(e10, e11);
        ph[ks][3] = pack2(e12, e13);
        pl[ks][0] = pack2(e00 - bflo(ph[ks][0]), e01 - bfhi(ph[ks][0]));
        pl[ks][1] = pack2(e02 - bflo(ph[ks][1]), e03 - bfhi(ph[ks][1]));
        pl[ks][2] = pack2(e10 - bflo(ph[ks][2]), e11 - bfhi(ph[ks][2]));
        pl[ks][3] = pack2(e12 - bflo(ph[ks][3]), e13 - bfhi(ph[ks][3]));
    }
    smA += __shfl_xor_sync(0xffffffffu, smA, 1);
    smA += __shfl_xor_sync(0xffffffffu, smA, 2);
    smB += __shfl_xor_sync(0xffffffffu, smB, 1);
    smB += __shfl_xor_sync(0xffffffffu, smB, 2);
    const float rinvA = 1.f / smA, rinvB = 1.f / smB;
    // P left unnormalized; 1/sum folded into the O store.

    // ---- PV: O[16 x 32] per warp; B = V from [d][m] smem ----
    float O[4][4];
#pragma unroll
    for (int t = 0; t < 4; t++)
#pragma unroll
        for (int c = 0; c < 4; c++) O[t][c] = 0.f;

#pragma unroll
    for (int dt = 0; dt < 4; dt++) {
#pragma unroll
        for (int ks = 0; ks < 4; ks++) {
            const unsigned* vp = svw + (dt * 8 + r) * 68 + 8 * ks + cq;
            unsigned bh0 = vp[0], bh1 = vp[4];
            unsigned bl0 = vp[32], bl1 = vp[36];
            MMA(O[dt], ph[ks], bh0, bh1);
            MMA(O[dt], ph[ks], bl0, bl1);
            MMA(O[dt], pl[ks], bh0, bh1);
        }
    }

    // ---- store O (normalize by 1/sum here) ----
    const int yA = (y0 + 2 * wrp) & 255;
    const int yB = (y0 + 2 * wrp + 1) & 255;
    const int xj = (x0 + r) & 255;
#pragma unroll
    for (int dt = 0; dt < 4; dt++) {
        const int d = dt * 8 + 2 * cq;
        out[(chbase + d) * HW + yA * 256 + xj]     = O[dt][0] * rinvA;
        out[(chbase + d + 1) * HW + yA * 256 + xj] = O[dt][1] * rinvA;
        out[(chbase + d) * HW + yB * 256 + xj]     = O[dt][2] * rinvB;
        out[(chbase + d + 1) * HW + yB * 256 + xj] = O[dt][3] * rinvB;
    }
}

// ---------------------------------------------------------------------------
extern "C" void kernel_launch(void* const* d_in, const int* in_sizes, int n_in,
                              void* d_out, int out_size) {
    const float* qkv         = (const float*)d_in[0];
    const float* table       = (const float*)d_in[1];
    const int*   index       = (const int*)  d_in[2];
    const float* mask        = (const float*)d_in[3];
    const float* logit_scale = (const float*)d_in[4];
    const float* w1          = (const float*)d_in[5];
    const float* b1          = (const float*)d_in[6];
    const float* w2          = (const float*)d_in[7];
    float* out = (float*)d_out;

    const int smem_bytes = SMEM_WORDS * 4;   // 54528
    cudaFuncSetAttribute(win_attn_kernel,
                         cudaFuncAttributeMaxDynamicSharedMemorySize, smem_bytes);
    cudaFuncSetAttribute(win_attn_kernel,
                         cudaFuncAttributePreferredSharedMemoryCarveout, 100);

    bias_mlp_kernel<<<TBL, 128>>>(table, logit_scale, w1, b1, w2);
    bias_gather_kernel<<<96, 256>>>(index);

    float* d_bias = nullptr;
    cudaGetSymbolAddress((void**)&d_bias, g_bias);
    win_attn_kernel<<<1024 * NH, 256, smem_bytes>>>(qkv, mask, d_bias, out);
    (void)in_sizes; (void)n_in; (void)out_size;
}

// round 16
// speedup vs baseline: 1.4741x; 1.4741x over previous
#include <cuda_runtime.h>
#include <cuda_bf16.h>

#define NH 6
#define HD 32
#define NTOK 64
#define HIDDEN 512
#define TBL 225
#define HW 65536

// Per-window Q/K buffer: row n at n*36 + ((n>>2)&15) words; 64 rows + pad.
#define STQK 36
#define SWQK(n) ((n) * STQK + (((n) >> 2) & 15))
#define QKW 2320          // words per Q or K window buffer (64*36+16)
// V: [32][68] words; words 0..31 = m-pair hi, 32..63 = lo.
#define VW 2176           // 32*68
// bias (pre-scaled by log2e) fp32: [64][68] -- shared by both windows (head-only)
#define BW 4352           // 64*68
#define LOG2E 1.4426950408889634f

// dynamic smem word offsets (2 windows per CTA)
#define OFF_SQ 0
#define OFF_SK (2 * QKW)                 // 4640
#define OFF_SV (4 * QKW)                 // 9280
#define OFF_SB (4 * QKW + 2 * VW)        // 13632
#define SMEM_WORDS (OFF_SB + BW)         // 17984 words = 71936 B

// m16n8k16 row.col f32.bf16.bf16.f32
#define MMA(D, A, b0, b1) \
    asm("mma.sync.aligned.m16n8k16.row.col.f32.bf16.bf16.f32 " \
        "{%0,%1,%2,%3},{%4,%5,%6,%7},{%8,%9},{%0,%1,%2,%3};" \
        : "+f"(D[0]), "+f"(D[1]), "+f"(D[2]), "+f"(D[3]) \
        : "r"(A[0]), "r"(A[1]), "r"(A[2]), "r"(A[3]), "r"(b0), "r"(b1))

__device__ __forceinline__ unsigned pack2(float lo, float hi) {
    unsigned r;
    asm("cvt.rn.bf16x2.f32 %0, %1, %2;" : "=r"(r) : "f"(hi), "f"(lo));
    return r;  // low half = lo, high half = hi
}
__device__ __forceinline__ float bflo(unsigned w) { return __uint_as_float(w << 16); }
__device__ __forceinline__ float bfhi(unsigned w) { return __uint_as_float(w & 0xffff0000u); }
__device__ __forceinline__ float ex2f(float x) {
    float y;
    asm("ex2.approx.ftz.f32 %0, %1;" : "=f"(y) : "f"(x));
    return y;
}
__device__ __forceinline__ unsigned smem_u32(const void* p) {
    return (unsigned)__cvta_generic_to_shared(p);
}

// device-global scratch (no allocations allowed)
__device__ float g_bt[TBL * NH];
__device__ float g_hscale[NH];       // exp(min(ls,max)) * rsqrt(hd) * log2e
__device__ float g_bias[NH * NTOK * NTOK];  // 16*sigmoid(..) * log2e

// ---------------------------------------------------------------------------
// Kernel 0a: CPB MLP, one block per table row (225 blocks) + head scales.
// ---------------------------------------------------------------------------
__global__ void __launch_bounds__(128) bias_mlp_kernel(
    const float* __restrict__ table,
    const float* __restrict__ logit_scale,
    const float* __restrict__ w1,
    const float* __restrict__ b1,
    const float* __restrict__ w2) {
    const int row = blockIdx.x;
    const int tid = threadIdx.x;

    if (row == 0 && tid < NH) {
        const float LOGIT_MAX = 4.605170185988091368f; // log(100)
        g_hscale[tid] = expf(fminf(logit_scale[tid], LOGIT_MAX)) * rsqrtf((float)HD) * LOG2E;
    }

    const float t0 = table[row * 2 + 0];
    const float t1 = table[row * 2 + 1];
    float acc[NH];
#pragma unroll
    for (int h = 0; h < NH; h++) acc[h] = 0.f;

    for (int j = tid; j < HIDDEN; j += 128) {
        float hv = fmaf(t0, w1[j], fmaf(t1, w1[HIDDEN + j], b1[j]));
        hv = fmaxf(hv, 0.f);
#pragma unroll
        for (int h = 0; h < NH; h++) acc[h] = fmaf(hv, w2[j * NH + h], acc[h]);
    }

#pragma unroll
    for (int h = 0; h < NH; h++) {
#pragma unroll
        for (int o = 16; o > 0; o >>= 1)
            acc[h] += __shfl_xor_sync(0xffffffffu, acc[h], o);
    }
    __shared__ float red[4][NH];
    const int warp = tid >> 5;
    if ((tid & 31) == 0) {
#pragma unroll
        for (int h = 0; h < NH; h++) red[warp][h] = acc[h];
    }
    __syncthreads();
    if (tid == 0) {
#pragma unroll
        for (int h = 0; h < NH; h++)
            g_bt[row * NH + h] = red[0][h] + red[1][h] + red[2][h] + red[3][h];
    }
}

// ---------------------------------------------------------------------------
// Kernel 0b: expand bias -> g_bias[h][n][m] = 16*sigmoid(bt[idx][h]) * log2e
// ---------------------------------------------------------------------------
__global__ void bias_gather_kernel(const int* __restrict__ index) {
    int gid = blockIdx.x * blockDim.x + threadIdx.x;
    if (gid >= NH * NTOK * NTOK) return;
    int h = gid >> 12;
    int nm = gid & 4095;
    int r = index[nm];
    float bv = g_bt[r * NH + h];
    g_bias[gid] = (16.f / (1.f + __expf(-bv))) * LOG2E;
}

// ---------------------------------------------------------------------------
// Main kernel: one CTA per (2-window strip, head). 256 threads, 3 CTAs/SM.
//  Strip-coalesced staging; bf16x3 mma.sync; bias staged via cp.async,
//  mask read directly from L2 in the epilogue.  (R14 config + cp.async.)
// ---------------------------------------------------------------------------
__global__ void __launch_bounds__(256, 3) win_attn_kernel(
    const float* __restrict__ qkv,
    const float* __restrict__ mask,
    const float* __restrict__ bias,
    float* __restrict__ out)
{
    extern __shared__ __align__(16) unsigned dyn[];
    unsigned* const sq_all = dyn + OFF_SQ;
    unsigned* const sk_all = dyn + OFF_SK;
    unsigned* const sv_all = dyn + OFF_SV;
    float* const sb = (float*)(dyn + OFF_SB);   // bias, shared by both windows

    const int tid = threadIdx.x;
    const int bid = blockIdx.x;
    const int h = bid % NH;
    const int s = bid / NH;             // 0..1023 strips
    const int b = s >> 9;               // batch
    const int sl = s & 511;
    const int wy = sl >> 4;             // window row 0..31
    const int sx = sl & 15;             // strip col 0..15 (2 windows each)
    const int y0 = wy * 8 + 4;
    const int x0s = sx * 16 + 4;        // strip x origin (shifted by roll)

    // channel = t*384 + b*192 + h*32 + d   (qkv is (3,B,192,H,W))
    const int chbase = b * 192 + h * 32;

    const float* bias_h = bias + h * 4096;

    // ---- stage bias via cp.async (fully async under Q/K/V staging) ----
#pragma unroll
    for (int l = 0; l < 4; l++) {
        int u = tid + l * 256;          // 0..1023 float4
        int n = u >> 4;
        int mq = (u & 15) << 2;
        unsigned dst = smem_u32(&sb[n * 68 + mq]);
        const float* src = bias_h + n * 64 + mq;
        asm volatile("cp.async.cg.shared.global [%0], [%1], 16;"
                     :: "r"(dst), "l"(src) : "memory");
    }
    asm volatile("cp.async.commit_group;" ::: "memory");

    // ---- stage Q,K: strip-coalesced; unit = (tensor, k-pair, row, float4col) ----
#pragma unroll
    for (int l = 0; l < 4; l++) {
        int u = tid + l * 256;          // 0..1023
        int t = u >> 9;                 // 0 = q, 1 = k
        int rem = u & 511;
        int kp = rem >> 5;              // 0..15
        int i = (rem >> 2) & 7;         // window row
        int o4 = rem & 3;               // float4 col within strip (2 windows)
        int y = (y0 + i) & 255;
        int x = (x0s + 4 * o4) & 255;   // 4-aligned; no intra-float4 wrap
        const float* basep = qkv + (chbase + t * 384 + 2 * kp) * HW + y * 256 + x;
        float4 v0 = *(const float4*)basep;          // channel 2*kp
        float4 v1 = *(const float4*)(basep + HW);   // channel 2*kp+1
        int wloc = o4 >> 1;
        int j0 = (o4 & 1) << 2;
        int n = i * 8 + j0;
        unsigned* rowbase = ((t == 0) ? sq_all : sk_all) + wloc * QKW;
        float a0[4] = {v0.x, v0.y, v0.z, v0.w};
        float a1[4] = {v1.x, v1.y, v1.z, v1.w};
#pragma unroll
        for (int e = 0; e < 4; e++) {
            unsigned hw_ = pack2(a0[e], a1[e]);
            unsigned lw_ = pack2(a0[e] - bflo(hw_), a1[e] - bfhi(hw_));
            int ro = SWQK(n + e);
            rowbase[ro + kp] = hw_;
            rowbase[ro + 16 + kp] = lw_;
        }
    }
    // ---- stage V: strip-coalesced ----
#pragma unroll
    for (int l = 0; l < 4; l++) {
        int u = tid + l * 256;          // 0..1023
        int d = u >> 5;                 // 0..31
        int i = (u >> 2) & 7;
        int o4 = u & 3;
        int y = (y0 + i) & 255;
        int x = (x0s + 4 * o4) & 255;
        float4 v = *(const float4*)(qkv + (chbase + 768 + d) * HW + y * 256 + x);
        int wloc = o4 >> 1;
        int j0 = (o4 & 1) << 2;
        int n = i * 8 + j0;
        unsigned* svw = sv_all + wloc * VW;
        unsigned h0 = pack2(v.x, v.y);
        unsigned h1 = pack2(v.z, v.w);
        unsigned l0 = pack2(v.x - bflo(h0), v.y - bfhi(h0));
        unsigned l1 = pack2(v.z - bflo(h1), v.w - bfhi(h1));
        *(uint2*)&svw[d * 68 + (n >> 1)] = make_uint2(h0, h1);
        *(uint2*)&svw[d * 68 + 32 + (n >> 1)] = make_uint2(l0, l1);
    }
    asm volatile("cp.async.wait_group 0;" ::: "memory");
    __syncthreads();

    const int lane = tid & 31;
    const int wid = tid >> 5;           // 0..7
    const int wloc = wid >> 2;          // window slot 0..1
    const int wrp = wid & 3;            // warp within window
    const int r = lane >> 2;            // groupID
    const int cq = lane & 3;            // threadID in group
    const int rowA = wrp * 16 + r;      // token row (half A); half B = +8

    const unsigned* sqw = sq_all + wloc * QKW;
    const unsigned* skw = sk_all + wloc * QKW;
    const unsigned* svw = sv_all + wloc * VW;
    const float* mask_w = mask + (wy * 32 + sx * 2 + wloc) * 4096;
    const int x0 = x0s + 8 * wloc;      // this window's x origin

    // ---- QK^T: A fragments (Q) hoisted; 8 n-tiles x 2 k-steps x 3 splits ----
    unsigned ah[2][4], al[2][4];
#pragma unroll
    for (int ks = 0; ks < 2; ks++) {
        const unsigned* q0 = sqw + SWQK(rowA) + 8 * ks + cq;
        const unsigned* q1 = sqw + SWQK(rowA + 8) + 8 * ks + cq;
        ah[ks][0] = q0[0];  ah[ks][1] = q1[0];  ah[ks][2] = q0[4];  ah[ks][3] = q1[4];
        al[ks][0] = q0[16]; al[ks][1] = q1[16]; al[ks][2] = q0[20]; al[ks][3] = q1[20];
    }

    float D[8][4];
#pragma unroll
    for (int t = 0; t < 8; t++)
#pragma unroll
        for (int c = 0; c < 4; c++) D[t][c] = 0.f;

#pragma unroll
    for (int nt = 0; nt < 8; nt++) {
#pragma unroll
        for (int ks = 0; ks < 2; ks++) {
            const unsigned* kp = skw + SWQK(nt * 8 + r) + 8 * ks + cq;
            unsigned bh0 = kp[0], bh1 = kp[4];
            unsigned bl0 = kp[16], bl1 = kp[20];
            MMA(D[nt], ah[ks], bh0, bh1);
            MMA(D[nt], ah[ks], bl0, bl1);
            MMA(D[nt], al[ks], bh0, bh1);
        }
    }

    // ---- softmax IN PLACE in D, log2 domain; bias from smem, mask from L2 ----
    const float scale2 = g_hscale[h];   // includes log2e
    const float* bA_p = sb + rowA * 68 + 2 * cq;
    const float* bB_p = sb + (rowA + 8) * 68 + 2 * cq;
    const float* mA_p = mask_w + rowA * 64 + 2 * cq;
    const float* mB_p = mask_w + (rowA + 8) * 64 + 2 * cq;
#pragma unroll
    for (int t = 0; t < 8; t++) {
        float2 bA = *(const float2*)(bA_p + t * 8);
        float2 mA = *(const float2*)(mA_p + t * 8);
        float2 bB = *(const float2*)(bB_p + t * 8);
        float2 mB = *(const float2*)(mB_p + t * 8);
        D[t][0] = fmaf(D[t][0], scale2, fmaf(mA.x, LOG2E, bA.x));
        D[t][1] = fmaf(D[t][1], scale2, fmaf(mA.y, LOG2E, bA.y));
        D[t][2] = fmaf(D[t][2], scale2, fmaf(mB.x, LOG2E, bB.x));
        D[t][3] = fmaf(D[t][3], scale2, fmaf(mB.y, LOG2E, bB.y));
    }
    float mxA = -1e30f, mxB = -1e30f;
#pragma unroll
    for (int t = 0; t < 8; t++) {
        mxA = fmaxf(mxA, fmaxf(D[t][0], D[t][1]));
        mxB = fmaxf(mxB, fmaxf(D[t][2], D[t][3]));
    }
    mxA = fmaxf(mxA, __shfl_xor_sync(0xffffffffu, mxA, 1));
    mxA = fmaxf(mxA, __shfl_xor_sync(0xffffffffu, mxA, 2));
    mxB = fmaxf(mxB, __shfl_xor_sync(0xffffffffu, mxB, 1));
    mxB = fmaxf(mxB, __shfl_xor_sync(0xffffffffu, mxB, 2));

    // progressive: exp, sum, pack P (hi/lo); D dies as ph/pl born
    unsigned ph[4][4], pl[4][4];
    float smA = 0.f, smB = 0.f;
#pragma unroll
    for (int ks = 0; ks < 4; ks++) {
        float e00 = ex2f(D[2 * ks][0] - mxA);
        float e01 = ex2f(D[2 * ks][1] - mxA);
        float e02 = ex2f(D[2 * ks][2] - mxB);
        float e03 = ex2f(D[2 * ks][3] - mxB);
        float e10 = ex2f(D[2 * ks + 1][0] - mxA);
        float e11 = ex2f(D[2 * ks + 1][1] - mxA);
        float e12 = ex2f(D[2 * ks + 1][2] - mxB);
        float e13 = ex2f(D[2 * ks + 1][3] - mxB);
        smA += e00 + e01 + e10 + e11;
        smB += e02 + e03 + e12 + e13;
        ph[ks][0] = pack2(e00, e01);
        ph[ks][1] = pack2(e02, e03);
        ph[ks][2] = pack2(e10, e11);
        ph[ks][3] = pack2(e12, e13);
        pl[ks][0] = pack2(e00 - bflo(ph[ks][0]), e01 - bfhi(ph[ks][0]));
        pl[ks][1] = pack2(e02 - bflo(ph[ks][1]), e03 - bfhi(ph[ks][1]));
        pl[ks][2] = pack2(e10 - bflo(ph[ks][2]), e11 - bfhi(ph[ks][2]));
        pl[ks][3] = pack2(e12 - bflo(ph[ks][3]), e13 - bfhi(ph[ks][3]));
    }
    smA += __shfl_xor_sync(0xffffffffu, smA, 1);
    smA += __shfl_xor_sync(0xffffffffu, smA, 2);
    smB += __shfl_xor_sync(0xffffffffu, smB, 1);
    smB += __shfl_xor_sync(0xffffffffu, smB, 2);
    const float rinvA = 1.f / smA, rinvB = 1.f / smB;
    // P left unnormalized; 1/sum folded into the O store.

    // ---- PV: O[16 x 32] per warp; B = V from [d][m] smem ----
    float O[4][4];
#pragma unroll
    for (int t = 0; t < 4; t++)
#pragma unroll
        for (int c = 0; c < 4; c++) O[t][c] = 0.f;

#pragma unroll
    for (int dt = 0; dt < 4; dt++) {
#pragma unroll
        for (int ks = 0; ks < 4; ks++) {
            const unsigned* vp = svw + (dt * 8 + r) * 68 + 8 * ks + cq;
            unsigned bh0 = vp[0], bh1 = vp[4];
            unsigned bl0 = vp[32], bl1 = vp[36];
            MMA(O[dt], ph[ks], bh0, bh1);
            MMA(O[dt], ph[ks], bl0, bl1);
            MMA(O[dt], pl[ks], bh0, bh1);
        }
    }

    // ---- store O (normalize by 1/sum here) ----
    const int yA = (y0 + 2 * wrp) & 255;
    const int yB = (y0 + 2 * wrp + 1) & 255;
    const int xj = (x0 + r) & 255;
#pragma unroll
    for (int dt = 0; dt < 4; dt++) {
        const int d = dt * 8 + 2 * cq;
        out[(chbase + d) * HW + yA * 256 + xj]     = O[dt][0] * rinvA;
        out[(chbase + d + 1) * HW + yA * 256 + xj] = O[dt][1] * rinvA;
        out[(chbase + d) * HW + yB * 256 + xj]     = O[dt][2] * rinvB;
        out[(chbase + d + 1) * HW + yB * 256 + xj] = O[dt][3] * rinvB;
    }
}

// ---------------------------------------------------------------------------
extern "C" void kernel_launch(void* const* d_in, const int* in_sizes, int n_in,
                              void* d_out, int out_size) {
    const float* qkv         = (const float*)d_in[0];
    const float* table       = (const float*)d_in[1];
    const int*   index       = (const int*)  d_in[2];
    const float* mask        = (const float*)d_in[3];
    const float* logit_scale = (const float*)d_in[4];
    const float* w1          = (const float*)d_in[5];
    const float* b1          = (const float*)d_in[6];
    const float* w2          = (const float*)d_in[7];
    float* out = (float*)d_out;

    const int smem_bytes = SMEM_WORDS * 4;   // 71936
    cudaFuncSetAttribute(win_attn_kernel,
                         cudaFuncAttributeMaxDynamicSharedMemorySize, smem_bytes);
    cudaFuncSetAttribute(win_attn_kernel,
                         cudaFuncAttributePreferredSharedMemoryCarveout, 100);

    bias_mlp_kernel<<<TBL, 128>>>(table, logit_scale, w1, b1, w2);
    bias_gather_kernel<<<96, 256>>>(index);

    float* d_bias = nullptr;
    cudaGetSymbolAddress((void**)&d_bias, g_bias);
    win_attn_kernel<<<1024 * NH, 256, smem_bytes>>>(qkv, mask, d_bias, out);
    (void)in_sizes; (void)n_in; (void)out_size;
}

// round 17
// speedup vs baseline: 1.5080x; 1.0230x over previous
#include <cuda_runtime.h>
#include <cuda_bf16.h>
#include <cuda_fp16.h>

#define NH 6
#define HD 32
#define NTOK 64
#define HIDDEN 512
#define TBL 225
#define HW 65536

// Per-window Q/K buffer: row n at n*36 + ((n>>2)&15) words; 64 rows + pad.
#define STQK 36
#define SWQK(n) ((n) * STQK + (((n) >> 2) & 15))
#define QKW 2320          // words per Q or K window buffer (64*36+16)
// V: [32][68] words; words 0..31 = m-pair hi (fp16x2), 32..63 = lo.
#define VW 2176           // 32*68
// bias (pre-scaled by log2e) fp32: [64][68] -- shared by both windows (head-only)
#define BW 4352           // 64*68
#define LOG2E 1.4426950408889634f

// dynamic smem word offsets (2 windows per CTA)
#define OFF_SQ 0
#define OFF_SK (2 * QKW)                 // 4640
#define OFF_SV (4 * QKW)                 // 9280
#define OFF_SB (4 * QKW + 2 * VW)        // 13632
#define SMEM_WORDS (OFF_SB + BW)         // 17984 words = 71936 B

// m16n8k16 row.col f32.bf16.bf16.f32  (QK^T path)
#define MMA(D, A, b0, b1) \
    asm("mma.sync.aligned.m16n8k16.row.col.f32.bf16.bf16.f32 " \
        "{%0,%1,%2,%3},{%4,%5,%6,%7},{%8,%9},{%0,%1,%2,%3};" \
        : "+f"(D[0]), "+f"(D[1]), "+f"(D[2]), "+f"(D[3]) \
        : "r"(A[0]), "r"(A[1]), "r"(A[2]), "r"(A[3]), "r"(b0), "r"(b1))

// m16n8k16 row.col f32.f16.f16.f32  (PV path)
#define MMAH(D, A, b0, b1) \
    asm("mma.sync.aligned.m16n8k16.row.col.f32.f16.f16.f32 " \
        "{%0,%1,%2,%3},{%4,%5,%6,%7},{%8,%9},{%0,%1,%2,%3};" \
        : "+f"(D[0]), "+f"(D[1]), "+f"(D[2]), "+f"(D[3]) \
        : "r"(A[0]), "r"(A[1]), "r"(A[2]), "r"(A[3]), "r"(b0), "r"(b1))

__device__ __forceinline__ unsigned pack2(float lo, float hi) {
    unsigned r;
    asm("cvt.rn.bf16x2.f32 %0, %1, %2;" : "=r"(r) : "f"(hi), "f"(lo));
    return r;  // low half = lo, high half = hi
}
__device__ __forceinline__ float bflo(unsigned w) { return __uint_as_float(w << 16); }
__device__ __forceinline__ float bfhi(unsigned w) { return __uint_as_float(w & 0xffff0000u); }
__device__ __forceinline__ unsigned pack2h(float lo, float hi) {
    unsigned r;
    asm("cvt.rn.f16x2.f32 %0, %1, %2;" : "=r"(r) : "f"(hi), "f"(lo));
    return r;  // low half = lo, high half = hi
}
__device__ __forceinline__ float hlo(unsigned w) {
    __half2 h = *(__half2*)&w;
    return __low2float(h);
}
__device__ __forceinline__ float hhi(unsigned w) {
    __half2 h = *(__half2*)&w;
    return __high2float(h);
}
__device__ __forceinline__ float ex2f(float x) {
    float y;
    asm("ex2.approx.ftz.f32 %0, %1;" : "=f"(y) : "f"(x));
    return y;
}

// device-global scratch (no allocations allowed)
__device__ float g_bt[TBL * NH];
__device__ float g_hscale[NH];       // exp(min(ls,max)) * rsqrt(hd) * log2e
__device__ float g_bias[NH * NTOK * NTOK];  // 16*sigmoid(..) * log2e

// ---------------------------------------------------------------------------
// Kernel 0a: CPB MLP, one block per table row (225 blocks) + head scales.
// ---------------------------------------------------------------------------
__global__ void __launch_bounds__(128) bias_mlp_kernel(
    const float* __restrict__ table,
    const float* __restrict__ logit_scale,
    const float* __restrict__ w1,
    const float* __restrict__ b1,
    const float* __restrict__ w2) {
    const int row = blockIdx.x;
    const int tid = threadIdx.x;

    if (row == 0 && tid < NH) {
        const float LOGIT_MAX = 4.605170185988091368f; // log(100)
        g_hscale[tid] = expf(fminf(logit_scale[tid], LOGIT_MAX)) * rsqrtf((float)HD) * LOG2E;
    }

    const float t0 = table[row * 2 + 0];
    const float t1 = table[row * 2 + 1];
    float acc[NH];
#pragma unroll
    for (int h = 0; h < NH; h++) acc[h] = 0.f;

    for (int j = tid; j < HIDDEN; j += 128) {
        float hv = fmaf(t0, w1[j], fmaf(t1, w1[HIDDEN + j], b1[j]));
        hv = fmaxf(hv, 0.f);
#pragma unroll
        for (int h = 0; h < NH; h++) acc[h] = fmaf(hv, w2[j * NH + h], acc[h]);
    }

#pragma unroll
    for (int h = 0; h < NH; h++) {
#pragma unroll
        for (int o = 16; o > 0; o >>= 1)
            acc[h] += __shfl_xor_sync(0xffffffffu, acc[h], o);
    }
    __shared__ float red[4][NH];
    const int warp = tid >> 5;
    if ((tid & 31) == 0) {
#pragma unroll
        for (int h = 0; h < NH; h++) red[warp][h] = acc[h];
    }
    __syncthreads();
    if (tid == 0) {
#pragma unroll
        for (int h = 0; h < NH; h++)
            g_bt[row * NH + h] = red[0][h] + red[1][h] + red[2][h] + red[3][h];
    }
}

// ---------------------------------------------------------------------------
// Kernel 0b: expand bias -> g_bias[h][n][m] = 16*sigmoid(bt[idx][h]) * log2e
// ---------------------------------------------------------------------------
__global__ void bias_gather_kernel(const int* __restrict__ index) {
    int gid = blockIdx.x * blockDim.x + threadIdx.x;
    if (gid >= NH * NTOK * NTOK) return;
    int h = gid >> 12;
    int nm = gid & 4095;
    int r = index[nm];
    float bv = g_bt[r * NH + h];
    g_bias[gid] = (16.f / (1.f + __expf(-bv))) * LOG2E;
}

// ---------------------------------------------------------------------------
// Main kernel: one CTA per (2-window strip, head). 256 threads, 3 CTAs/SM.
//  QK^T: bf16x3 mma.sync.  PV: fp16 P (single) x fp16 V (hi/lo) = 2 MMAs.
//  Bias staged in smem; mask read from L2 in the epilogue.
// ---------------------------------------------------------------------------
__global__ void __launch_bounds__(256, 3) win_attn_kernel(
    const float* __restrict__ qkv,
    const float* __restrict__ mask,
    const float* __restrict__ bias,
    float* __restrict__ out)
{
    extern __shared__ __align__(16) unsigned dyn[];
    unsigned* const sq_all = dyn + OFF_SQ;
    unsigned* const sk_all = dyn + OFF_SK;
    unsigned* const sv_all = dyn + OFF_SV;
    float* const sb = (float*)(dyn + OFF_SB);   // bias, shared by both windows

    const int tid = threadIdx.x;
    const int bid = blockIdx.x;
    const int h = bid % NH;
    const int s = bid / NH;             // 0..1023 strips
    const int b = s >> 9;               // batch
    const int sl = s & 511;
    const int wy = sl >> 4;             // window row 0..31
    const int sx = sl & 15;             // strip col 0..15 (2 windows each)
    const int y0 = wy * 8 + 4;
    const int x0s = sx * 16 + 4;        // strip x origin (shifted by roll)

    // channel = t*384 + b*192 + h*32 + d   (qkv is (3,B,192,H,W))
    const int chbase = b * 192 + h * 32;

    const float* bias_h = bias + h * 4096;

    // ---- stage Q,K: strip-coalesced; unit = (tensor, k-pair, row, float4col) ----
#pragma unroll
    for (int l = 0; l < 4; l++) {
        int u = tid + l * 256;          // 0..1023
        int t = u >> 9;                 // 0 = q, 1 = k
        int rem = u & 511;
        int kp = rem >> 5;              // 0..15
        int i = (rem >> 2) & 7;         // window row
        int o4 = rem & 3;               // float4 col within strip (2 windows)
        int y = (y0 + i) & 255;
        int x = (x0s + 4 * o4) & 255;   // 4-aligned; no intra-float4 wrap
        const float* basep = qkv + (chbase + t * 384 + 2 * kp) * HW + y * 256 + x;
        float4 v0 = *(const float4*)basep;          // channel 2*kp
        float4 v1 = *(const float4*)(basep + HW);   // channel 2*kp+1
        int wloc = o4 >> 1;
        int j0 = (o4 & 1) << 2;
        int n = i * 8 + j0;
        unsigned* rowbase = ((t == 0) ? sq_all : sk_all) + wloc * QKW;
        float a0[4] = {v0.x, v0.y, v0.z, v0.w};
        float a1[4] = {v1.x, v1.y, v1.z, v1.w};
#pragma unroll
        for (int e = 0; e < 4; e++) {
            unsigned hw_ = pack2(a0[e], a1[e]);
            unsigned lw_ = pack2(a0[e] - bflo(hw_), a1[e] - bfhi(hw_));
            int ro = SWQK(n + e);
            rowbase[ro + kp] = hw_;
            rowbase[ro + 16 + kp] = lw_;
        }
    }
    // ---- stage V: strip-coalesced, fp16 hi/lo ----
#pragma unroll
    for (int l = 0; l < 4; l++) {
        int u = tid + l * 256;          // 0..1023
        int d = u >> 5;                 // 0..31
        int i = (u >> 2) & 7;
        int o4 = u & 3;
        int y = (y0 + i) & 255;
        int x = (x0s + 4 * o4) & 255;
        float4 v = *(const float4*)(qkv + (chbase + 768 + d) * HW + y * 256 + x);
        int wloc = o4 >> 1;
        int j0 = (o4 & 1) << 2;
        int n = i * 8 + j0;
        unsigned* svw = sv_all + wloc * VW;
        unsigned h0 = pack2h(v.x, v.y);
        unsigned h1 = pack2h(v.z, v.w);
        unsigned l0 = pack2h(v.x - hlo(h0), v.y - hhi(h0));
        unsigned l1 = pack2h(v.z - hlo(h1), v.w - hhi(h1));
        *(uint2*)&svw[d * 68 + (n >> 1)] = make_uint2(h0, h1);
        *(uint2*)&svw[d * 68 + 32 + (n >> 1)] = make_uint2(l0, l1);
    }
    // ---- stage bias (pre-scaled by log2e), shared by both windows ----
#pragma unroll
    for (int l = 0; l < 4; l++) {
        int u = tid + l * 256;          // 0..1023 float4
        int n = u >> 4;
        int mq = (u & 15) << 2;
        float4 bv = *(const float4*)(bias_h + n * 64 + mq);
        *(float4*)&sb[n * 68 + mq] = bv;
    }
    __syncthreads();

    const int lane = tid & 31;
    const int wid = tid >> 5;           // 0..7
    const int wloc = wid >> 2;          // window slot 0..1
    const int wrp = wid & 3;            // warp within window
    const int r = lane >> 2;            // groupID
    const int cq = lane & 3;            // threadID in group
    const int rowA = wrp * 16 + r;      // token row (half A); half B = +8

    const unsigned* sqw = sq_all + wloc * QKW;
    const unsigned* skw = sk_all + wloc * QKW;
    const unsigned* svw = sv_all + wloc * VW;
    const float* mask_w = mask + (wy * 32 + sx * 2 + wloc) * 4096;
    const int x0 = x0s + 8 * wloc;      // this window's x origin

    // ---- QK^T: A fragments (Q) hoisted; 8 n-tiles x 2 k-steps x 3 splits ----
    unsigned ah[2][4], al[2][4];
#pragma unroll
    for (int ks = 0; ks < 2; ks++) {
        const unsigned* q0 = sqw + SWQK(rowA) + 8 * ks + cq;
        const unsigned* q1 = sqw + SWQK(rowA + 8) + 8 * ks + cq;
        ah[ks][0] = q0[0];  ah[ks][1] = q1[0];  ah[ks][2] = q0[4];  ah[ks][3] = q1[4];
        al[ks][0] = q0[16]; al[ks][1] = q1[16]; al[ks][2] = q0[20]; al[ks][3] = q1[20];
    }

    float D[8][4];
#pragma unroll
    for (int t = 0; t < 8; t++)
#pragma unroll
        for (int c = 0; c < 4; c++) D[t][c] = 0.f;

#pragma unroll
    for (int nt = 0; nt < 8; nt++) {
#pragma unroll
        for (int ks = 0; ks < 2; ks++) {
            const unsigned* kp = skw + SWQK(nt * 8 + r) + 8 * ks + cq;
            unsigned bh0 = kp[0], bh1 = kp[4];
            unsigned bl0 = kp[16], bl1 = kp[20];
            MMA(D[nt], ah[ks], bh0, bh1);
            MMA(D[nt], ah[ks], bl0, bl1);
            MMA(D[nt], al[ks], bh0, bh1);
        }
    }

    // ---- softmax IN PLACE in D, log2 domain; bias from smem, mask from L2 ----
    const float scale2 = g_hscale[h];   // includes log2e
    const float* bA_p = sb + rowA * 68 + 2 * cq;
    const float* bB_p = sb + (rowA + 8) * 68 + 2 * cq;
    const float* mA_p = mask_w + rowA * 64 + 2 * cq;
    const float* mB_p = mask_w + (rowA + 8) * 64 + 2 * cq;
#pragma unroll
    for (int t = 0; t < 8; t++) {
        float2 bA = *(const float2*)(bA_p + t * 8);
        float2 mA = *(const float2*)(mA_p + t * 8);
        float2 bB = *(const float2*)(bB_p + t * 8);
        float2 mB = *(const float2*)(mB_p + t * 8);
        D[t][0] = fmaf(D[t][0], scale2, fmaf(mA.x, LOG2E, bA.x));
        D[t][1] = fmaf(D[t][1], scale2, fmaf(mA.y, LOG2E, bA.y));
        D[t][2] = fmaf(D[t][2], scale2, fmaf(mB.x, LOG2E, bB.x));
        D[t][3] = fmaf(D[t][3], scale2, fmaf(mB.y, LOG2E, bB.y));
    }
    float mxA = -1e30f, mxB = -1e30f;
#pragma unroll
    for (int t = 0; t < 8; t++) {
        mxA = fmaxf(mxA, fmaxf(D[t][0], D[t][1]));
        mxB = fmaxf(mxB, fmaxf(D[t][2], D[t][3]));
    }
    mxA = fmaxf(mxA, __shfl_xor_sync(0xffffffffu, mxA, 1));
    mxA = fmaxf(mxA, __shfl_xor_sync(0xffffffffu, mxA, 2));
    mxB = fmaxf(mxB, __shfl_xor_sync(0xffffffffu, mxB, 1));
    mxB = fmaxf(mxB, __shfl_xor_sync(0xffffffffu, mxB, 2));

    // progressive: exp, sum, pack P as fp16 (single); D dies as ph born
    unsigned ph[4][4];
    float smA = 0.f, smB = 0.f;
#pragma unroll
    for (int ks = 0; ks < 4; ks++) {
        float e00 = ex2f(D[2 * ks][0] - mxA);
        float e01 = ex2f(D[2 * ks][1] - mxA);
        float e02 = ex2f(D[2 * ks][2] - mxB);
        float e03 = ex2f(D[2 * ks][3] - mxB);
        float e10 = ex2f(D[2 * ks + 1][0] - mxA);
        float e11 = ex2f(D[2 * ks + 1][1] - mxA);
        float e12 = ex2f(D[2 * ks + 1][2] - mxB);
        float e13 = ex2f(D[2 * ks + 1][3] - mxB);
        smA += e00 + e01 + e10 + e11;
        smB += e02 + e03 + e12 + e13;
        ph[ks][0] = pack2h(e00, e01);
        ph[ks][1] = pack2h(e02, e03);
        ph[ks][2] = pack2h(e10, e11);
        ph[ks][3] = pack2h(e12, e13);
    }
    smA += __shfl_xor_sync(0xffffffffu, smA, 1);
    smA += __shfl_xor_sync(0xffffffffu, smA, 2);
    smB += __shfl_xor_sync(0xffffffffu, smB, 1);
    smB += __shfl_xor_sync(0xffffffffu, smB, 2);
    const float rinvA = 1.f / smA, rinvB = 1.f / smB;
    // P left unnormalized; 1/sum folded into the O store.

    // ---- PV: O[16 x 32] per warp; B = V (fp16 hi/lo) from [d][m] smem ----
    float O[4][4];
#pragma unroll
    for (int t = 0; t < 4; t++)
#pragma unroll
        for (int c = 0; c < 4; c++) O[t][c] = 0.f;

#pragma unroll
    for (int dt = 0; dt < 4; dt++) {
#pragma unroll
        for (int ks = 0; ks < 4; ks++) {
            const unsigned* vp = svw + (dt * 8 + r) * 68 + 8 * ks + cq;
            unsigned bh0 = vp[0], bh1 = vp[4];
            unsigned bl0 = vp[32], bl1 = vp[36];
            MMAH(O[dt], ph[ks], bh0, bh1);
            MMAH(O[dt], ph[ks], bl0, bl1);
        }
    }

    // ---- store O (normalize by 1/sum here) ----
    const int yA = (y0 + 2 * wrp) & 255;
    const int yB = (y0 + 2 * wrp + 1) & 255;
    const int xj = (x0 + r) & 255;
#pragma unroll
    for (int dt = 0; dt < 4; dt++) {
        const int d = dt * 8 + 2 * cq;
        out[(chbase + d) * HW + yA * 256 + xj]     = O[dt][0] * rinvA;
        out[(chbase + d + 1) * HW + yA * 256 + xj] = O[dt][1] * rinvA;
        out[(chbase + d) * HW + yB * 256 + xj]     = O[dt][2] * rinvB;
        out[(chbase + d + 1) * HW + yB * 256 + xj] = O[dt][3] * rinvB;
    }
}

// ---------------------------------------------------------------------------
extern "C" void kernel_launch(void* const* d_in, const int* in_sizes, int n_in,
                              void* d_out, int out_size) {
    const float* qkv         = (const float*)d_in[0];
    const float* table       = (const float*)d_in[1];
    const int*   index       = (const int*)  d_in[2];
    const float* mask        = (const float*)d_in[3];
    const float* logit_scale = (const float*)d_in[4];
    const float* w1          = (const float*)d_in[5];
    const float* b1          = (const float*)d_in[6];
    const float* w2          = (const float*)d_in[7];
    float* out = (float*)d_out;

    const int smem_bytes = SMEM_WORDS * 4;   // 71936
    cudaFuncSetAttribute(win_attn_kernel,
                         cudaFuncAttributeMaxDynamicSharedMemorySize, smem_bytes);
    cudaFuncSetAttribute(win_attn_kernel,
                         cudaFuncAttributePreferredSharedMemoryCarveout, 100);

    bias_mlp_kernel<<<TBL, 128>>>(table, logit_scale, w1, b1, w2);
    bias_gather_kernel<<<96, 256>>>(index);

    float* d_bias = nullptr;
    cudaGetSymbolAddress((void**)&d_bias, g_bias);
    win_attn_kernel<<<1024 * NH, 256, smem_bytes>>>(qkv, mask, d_bias, out);
    (void)in_sizes; (void)n_in; (void)out_size;
}